// round 11
// baseline (speedup 1.0000x reference)
#include <cuda_runtime.h>
#include <cuda_bf16.h>

#define BN 8192
#define EN 8
#define HN 128
#define TS 128
#define NT (BN / TS)                 // 64 tiles per dim
#define NPAIR (NT * (NT + 1) / 2)    // 2080 upper-triangular tile pairs
#define GRID_PAIR 296                // 2 CTAs/SM, one wave
#define PREP_BLKS (BN / 8)           // 1024

// dynamic smem layout (bytes)
#define SM_STAGE   8192              // 4KB A + 4KB B per stage (fp8 k32 chunk)
#define SM_STAGES  (4 * SM_STAGE)    // 32768, 4 stages
#define SM_XI      (SM_STAGES)       // X tile, i side (4 KB)
#define SM_YJ      (SM_XI + 4096)    // Y tile, j side (4 KB)
#define SM_TOTAL   (SM_YJ + 4096)    // 40960

// ---------------- device scratch -------------------------------------------
// fp8(e4m3) sim-GEMM tile images in 4 K-chunks of 32 (32 B/row, 4 rows per
// 128B line, off16 swizzle). 4*64*4KB = 1 MB, L2-resident.
__device__ __align__(1024) unsigned char g_f8[4][NT][TS * 32];
// combined KL operand tiles, bf16, 16 cols/row (32 B), layout off16():
//   X_i = [logp_i - a_i (8), p_i (8)] ; Y_j = [p_j (8), logp_j - a_j (8)]
//   X_i . Y_j = -(kl(i,j) + kl(j,i))   (uses sum_e p = 1)
__device__ __align__(1024) unsigned char g_X16[NT][TS * 32];    // 256 KB
__device__ __align__(1024) unsigned char g_Y16[NT][TS * 32];    // 256 KB
// prep per-block partials (written unconditionally -> no zeroing kernel)
__device__ double g_pp_task[PREP_BLKS], g_pp_eff[PREP_BLKS], g_pp_ent[PREP_BLKS];
__device__ float  g_pp_us[PREP_BLKS * EN];
// pair per-CTA partials + never-reset ticket (modular check is replay-safe)
__device__ double g_pair_kl[GRID_PAIR];
__device__ double g_pair_cnt[GRID_PAIR];
__device__ unsigned g_ticket;

// ---------------- PTX helpers ----------------------------------------------
__device__ __forceinline__ unsigned smem_u32(const void* p) {
    unsigned a;
    asm("{ .reg .u64 t; cvta.to.shared.u64 t, %1; cvt.u32.u64 %0, t; }"
        : "=r"(a) : "l"(p));
    return a;
}
__device__ __forceinline__ void ldsm4(unsigned* r, unsigned addr) {
    asm volatile("ldmatrix.sync.aligned.m8n8.x4.shared.b16 {%0,%1,%2,%3}, [%4];"
                 : "=r"(r[0]), "=r"(r[1]), "=r"(r[2]), "=r"(r[3]) : "r"(addr));
}
__device__ __forceinline__ void mma16816(float* d, const unsigned* a, const unsigned* b) {
    asm volatile(
        "mma.sync.aligned.m16n8k16.row.col.f32.bf16.bf16.f32 "
        "{%0,%1,%2,%3}, {%4,%5,%6,%7}, {%8,%9}, {%0,%1,%2,%3};"
        : "+f"(d[0]), "+f"(d[1]), "+f"(d[2]), "+f"(d[3])
        : "r"(a[0]), "r"(a[1]), "r"(a[2]), "r"(a[3]), "r"(b[0]), "r"(b[1]));
}
__device__ __forceinline__ void mma16832f8(float* d, const unsigned* a, const unsigned* b) {
    asm volatile(
        "mma.sync.aligned.m16n8k32.row.col.f32.e4m3.e4m3.f32 "
        "{%0,%1,%2,%3}, {%4,%5,%6,%7}, {%8,%9}, {%0,%1,%2,%3};"
        : "+f"(d[0]), "+f"(d[1]), "+f"(d[2]), "+f"(d[3])
        : "r"(a[0]), "r"(a[1]), "r"(a[2]), "r"(a[3]), "r"(b[0]), "r"(b[1]));
}
__device__ __forceinline__ void cpa16(unsigned dst, const void* src) {
    asm volatile("cp.async.cg.shared.global [%0], [%1], 16;"
                 :: "r"(dst), "l"(src) : "memory");
}
#define CP_COMMIT() asm volatile("cp.async.commit_group;" ::: "memory")
#define CP_WAIT2()  asm volatile("cp.async.wait_group 2;" ::: "memory")
#define CP_WAIT0()  asm volatile("cp.async.wait_group 0;" ::: "memory")

// byte offset within a 128-row x 32B-row tile (4 rows/128B line, q in {0,1})
__device__ __forceinline__ unsigned off16(int r, int q) {
    return ((unsigned)(r >> 2) << 7) +
           ((((unsigned)(r & 3) << 1) + ((unsigned)q ^ ((unsigned)(r >> 2) & 1))) << 4);
}
__device__ __forceinline__ unsigned pkbf(float a, float b) {
    return (unsigned)__bfloat16_as_ushort(__float2bfloat16_rn(a)) |
           ((unsigned)__bfloat16_as_ushort(__float2bfloat16_rn(b)) << 16);
}
// pack 4 floats -> 4 e4m3 bytes (little-endian order x,y,z,w)
__device__ __forceinline__ unsigned pkf8(float x, float y, float z, float w) {
    unsigned short u0, u1;
    asm("cvt.rn.satfinite.e4m3x2.f32 %0, %1, %2;" : "=h"(u0) : "f"(y), "f"(x));
    asm("cvt.rn.satfinite.e4m3x2.f32 %0, %1, %2;" : "=h"(u1) : "f"(w), "f"(z));
    return (unsigned)u0 | ((unsigned)u1 << 16);
}
__device__ __forceinline__ double wredd(double v) {
#pragma unroll
    for (int o = 16; o > 0; o >>= 1) v += __shfl_xor_sync(0xffffffffu, v, o);
    return v;
}

// ---------------- per-row preprocessing + cheap loss partials ---------------
__global__ __launch_bounds__(256) void prep_kernel(
    const float* __restrict__ logits,
    const int* __restrict__ targets,
    const float* __restrict__ rp,
    const float* __restrict__ emb) {
    int warp = threadIdx.x >> 5, lane = threadIdx.x & 31;
    int row = blockIdx.x * 8 + warp;
    __shared__ float  s_us[EN];
    __shared__ double s_task[8], s_eff[8], s_ent[8];
    if (threadIdx.x < EN) s_us[threadIdx.x] = 0.f;
    __syncthreads();

    // normalize embedding row (float4 per lane = 4 consecutive k-cols)
    float4 v = *(const float4*)(emb + (size_t)row * HN + lane * 4);
    float ss = v.x * v.x + v.y * v.y + v.z * v.z + v.w * v.w;
#pragma unroll
    for (int o = 16; o > 0; o >>= 1) ss += __shfl_xor_sync(0xffffffffu, ss, o);
    float inv = rsqrtf(ss);
    float4 w = make_float4(v.x * inv, v.y * inv, v.z * inv, v.w * inv);

    // store e4m3 into chunked swizzled sim tile image
    {
        int cc = lane >> 3;                  // K-chunk 0..3 (32 cols each)
        int cb = (lane & 7) * 4;             // byte col within chunk (fp8)
        int q  = cb >> 4;
        int lr = row & (TS - 1);
        unsigned off = off16(lr, q) + (unsigned)(cb & 15);
        *(unsigned*)(&g_f8[cc][row >> 7][off]) = pkf8(w.x, w.y, w.z, w.w);
    }

    // routing-prob softmax over E=8
    float r = (lane < EN) ? rp[row * EN + lane] : -3.0e38f;
    float m = r;
#pragma unroll
    for (int o = 4; o > 0; o >>= 1) m = fmaxf(m, __shfl_xor_sync(0xffffffffu, m, o));
    float ex = (lane < EN) ? expf(r - m) : 0.f;
    float es = ex;
#pragma unroll
    for (int o = 4; o > 0; o >>= 1) es += __shfl_xor_sync(0xffffffffu, es, o);
    float lse = m + logf(es);
    float lp = r - lse;
    float p  = expf(lp);

    float av  = (lane < EN) ? p * lp : 0.f;
    float evv = (lane < EN && r < 0.1f) ? r : 0.f;
    float nv  = (lane < EN) ? r * logf(r + 1e-8f) : 0.f;
#pragma unroll
    for (int o = 4; o > 0; o >>= 1) {
        av  += __shfl_xor_sync(0xffffffffu, av, o);
        evv += __shfl_xor_sync(0xffffffffu, evv, o);
        nv  += __shfl_xor_sync(0xffffffffu, nv, o);
    }

    // build combined bf16 KL tiles:
    //   X = [logp - a (cols 0-7), p (cols 8-15)]
    //   Y = [p (cols 0-7), logp - a (cols 8-15)]
    {
        float l0 = __shfl_sync(0xffffffffu, lp, (lane & 3) * 2);
        float l1 = __shfl_sync(0xffffffffu, lp, (lane & 3) * 2 + 1);
        float p0 = __shfl_sync(0xffffffffu, p,  (lane & 3) * 2);
        float p1 = __shfl_sync(0xffffffffu, p,  (lane & 3) * 2 + 1);
        if (lane < 8) {
            unsigned lw = pkbf(l0 - av, l1 - av);
            unsigned pw = pkbf(p0, p1);
            unsigned Xw = (lane < 4) ? lw : pw;
            unsigned Yw = (lane < 4) ? pw : lw;
            int lr = row & (TS - 1);
            unsigned off = off16(lr, lane >> 2) + (unsigned)(lane & 3) * 4;
            *(unsigned*)(&g_X16[row >> 7][off]) = Xw;
            *(unsigned*)(&g_Y16[row >> 7][off]) = Yw;
        }
    }

    if (lane < EN) atomicAdd(&s_us[lane], r);
    if (lane == 0) {
        float l0 = logits[row * 3 + 0], l1 = logits[row * 3 + 1], l2 = logits[row * 3 + 2];
        float mm = fmaxf(l0, fmaxf(l1, l2));
        float lsm = mm + logf(expf(l0 - mm) + expf(l1 - mm) + expf(l2 - mm));
        int t = targets[row];
        float lt = (t == 0) ? l0 : ((t == 1) ? l1 : l2);
        s_task[warp] = (double)(lsm - lt);
        s_eff[warp]  = (double)evv;
        s_ent[warp]  = (double)nv;
    }
    __syncthreads();
    if (threadIdx.x == 0) {
        double a = 0, b = 0, c = 0;
        for (int i = 0; i < 8; i++) { a += s_task[i]; b += s_eff[i]; c += s_ent[i]; }
        g_pp_task[blockIdx.x] = a;
        g_pp_eff[blockIdx.x]  = b;
        g_pp_ent[blockIdx.x]  = c;
    }
    if (threadIdx.x < EN) g_pp_us[blockIdx.x * EN + threadIdx.x] = s_us[threadIdx.x];
}

// ---------------- FP8 pair kernel: 4-stage pipeline + bf16 KL epilogue ------
// Sim GEMM in e4m3 (m16n8k32): 4 K-chunks of 32, stage index == chunk index.
// Per chunk: wait_group 2 (group committed 3 iterations ago), sync, commit
// next (c==0: this tile's chunk3 + X/Y bundle; else next tile's chunk c-1),
// 6 ldsm + 16 mma. Epilogue: mask pack + ONE bf16 K=16 GEMM
//   D = X_i x Y_j^T = -(kl(i,j)+kl(j,i)), masked fold, 0.5x on diagonal.
__global__ __launch_bounds__(256, 2) void pair_kernel(
    const float* __restrict__ temperature, float* __restrict__ out) {
    extern __shared__ __align__(1024) unsigned char dsm[];
    __shared__ float s_rk[8];
    __shared__ int   s_rc[8];
    __shared__ double s_fin[6][8];
    __shared__ int s_last;

    int tid  = threadIdx.x;
    int wid  = tid >> 5;
    int lane = tid & 31;

    unsigned dbase = smem_u32(dsm);
    unsigned stA[4], stB[4];
#pragma unroll
    for (int s = 0; s < 4; s++) { stA[s] = dbase + s * SM_STAGE; stB[s] = stA[s] + 4096; }
    unsigned uXi = dbase + SM_XI, uYj = dbase + SM_YJ;

    int mbase = (wid & 3) * 32;
    int nbase = (wid >> 2) * 64;
    int rowA  = ((lane >> 3) & 1) * 8 + (lane & 7);
    int qselA = lane >> 4;
    int rowB  = ((lane >> 4) & 1) * 8 + (lane & 7);
    int qselB = (lane >> 3) & 1;

    // shared per-lane ldmatrix offsets (same off16 layout for fp8 and KL tiles)
    unsigned offA16[2], offB16[4];
#pragma unroll
    for (int mt = 0; mt < 2; mt++)
        offA16[mt] = off16(mbase + mt * 16 + rowA, qselA);
#pragma unroll
    for (int pnt = 0; pnt < 4; pnt++)
        offB16[pnt] = off16(nbase + pnt * 16 + rowB, qselB);

    unsigned co = (unsigned)tid * 16u;      // one cpa16 per thread per 4KB side

    float kls = 0.f;
    int   cnt = 0;

    // decode first tile
    int ti = 0, rem = blockIdx.x;
    while (rem >= NT - ti) { rem -= NT - ti; ti++; }
    int tj = ti + rem;

    // prologue: chunks 0,1,2 -> stages 0,1,2
#pragma unroll
    for (int c = 0; c < 3; c++) {
        cpa16(stA[c] + co, g_f8[c][ti] + co);
        cpa16(stB[c] + co, g_f8[c][tj] + co);
        CP_COMMIT();
    }

    for (int t = blockIdx.x; t < NPAIR; t += GRID_PAIR) {
        bool diag = (ti == tj);
        int ti2 = ti, tj2 = tj;
        bool more = (t + GRID_PAIR) < NPAIR;
        if (more) {
            int a = 0, r2 = t + GRID_PAIR;
            while (r2 >= NT - a) { r2 -= NT - a; a++; }
            ti2 = a; tj2 = a + r2;
        }

        float acc[2][8][4];
#pragma unroll
        for (int a = 0; a < 2; a++)
#pragma unroll
            for (int b = 0; b < 8; b++)
#pragma unroll
                for (int c = 0; c < 4; c++) acc[a][b][c] = 0.f;

#pragma unroll
        for (int c = 0; c < 4; c++) {
            CP_WAIT2();                 // group for chunk c (3 iterations old)
            __syncthreads();
            // commit 3 ahead
            if (c == 0) {               // this tile's chunk 3 + epilogue bundle
                cpa16(stA[3] + co, g_f8[3][ti] + co);
                cpa16(stB[3] + co, g_f8[3][tj] + co);
                cpa16(uXi + co, g_X16[ti] + co);
                cpa16(uYj + co, g_Y16[tj] + co);
            } else if (more) {          // next tile's chunk c-1 -> stage c-1
                cpa16(stA[c - 1] + co, g_f8[c - 1][ti2] + co);
                cpa16(stB[c - 1] + co, g_f8[c - 1][tj2] + co);
            }
            CP_COMMIT();                // always (empty groups at tail)

            // fp8 MMA on chunk c from stage c
            unsigned af[2][4], bf[4][4];
#pragma unroll
            for (int mt = 0; mt < 2; mt++) ldsm4(af[mt], stA[c] + offA16[mt]);
#pragma unroll
            for (int pnt = 0; pnt < 4; pnt++) ldsm4(bf[pnt], stB[c] + offB16[pnt]);
#pragma unroll
            for (int mt = 0; mt < 2; mt++)
#pragma unroll
                for (int pnt = 0; pnt < 4; pnt++) {
                    mma16832f8(acc[mt][pnt * 2 + 0], af[mt], &bf[pnt][0]);
                    mma16832f8(acc[mt][pnt * 2 + 1], af[mt], &bf[pnt][2]);
                }
        }

        // ---- pack threshold masks (diag branch hoisted) ----
        unsigned msk[2];
        if (!diag) {
#pragma unroll
            for (int mt = 0; mt < 2; mt++) {
                unsigned mw = 0;
#pragma unroll
                for (int nt = 0; nt < 8; nt++)
#pragma unroll
                    for (int q = 0; q < 4; q++)
                        mw |= (acc[mt][nt][q] > 0.8f ? 1u : 0u) << (nt * 4 + q);
                msk[mt] = mw;
            }
            cnt += 2 * (__popc(msk[0]) + __popc(msk[1]));
        } else {
#pragma unroll
            for (int mt = 0; mt < 2; mt++) {
                unsigned mw = 0;
#pragma unroll
                for (int nt = 0; nt < 8; nt++)
#pragma unroll
                    for (int q = 0; q < 4; q++) {
                        int il = mbase + mt * 16 + (q >> 1) * 8 + (lane >> 2);
                        int jl = nbase + nt * 8 + (lane & 3) * 2 + (q & 1);
                        bool pass = (acc[mt][nt][q] > 0.8f) && (il != jl);
                        mw |= (pass ? 1u : 0u) << (nt * 4 + q);
                    }
                msk[mt] = mw;
            }
            cnt += __popc(msk[0]) + __popc(msk[1]);
        }

        // ---- ONE bf16 K=16 GEMM: D = X_i x Y_j^T = -(kl(i,j)+kl(j,i)) ----
#pragma unroll
        for (int a = 0; a < 2; a++)
#pragma unroll
            for (int b = 0; b < 8; b++)
#pragma unroll
                for (int c = 0; c < 4; c++) acc[a][b][c] = 0.f;
        {
            unsigned af[2][4], bf[4][4];
#pragma unroll
            for (int mt = 0; mt < 2; mt++) ldsm4(af[mt], uXi + offA16[mt]);
#pragma unroll
            for (int pnt = 0; pnt < 4; pnt++) ldsm4(bf[pnt], uYj + offB16[pnt]);
#pragma unroll
            for (int mt = 0; mt < 2; mt++)
#pragma unroll
                for (int pnt = 0; pnt < 4; pnt++) {
                    mma16816(acc[mt][pnt * 2 + 0], af[mt], &bf[pnt][0]);
                    mma16816(acc[mt][pnt * 2 + 1], af[mt], &bf[pnt][2]);
                }
        }
        float S = 0.f;
#pragma unroll
        for (int mt = 0; mt < 2; mt++)
#pragma unroll
            for (int nt = 0; nt < 8; nt++)
#pragma unroll
                for (int q = 0; q < 4; q++)
                    S += ((msk[mt] >> (nt * 4 + q)) & 1u) ? acc[mt][nt][q] : 0.f;
        kls -= diag ? 0.5f * S : S;    // D = -(kl sum); diag double-counts pairs

        ti = ti2; tj = tj2;
    }
    CP_WAIT0();

    // ---- flush per-CTA partial ----
#pragma unroll
    for (int o = 16; o > 0; o >>= 1) {
        kls += __shfl_xor_sync(0xffffffffu, kls, o);
        cnt += __shfl_xor_sync(0xffffffffu, cnt, o);
    }
    if (lane == 0) { s_rk[wid] = kls; s_rc[wid] = cnt; }
    __syncthreads();
    if (tid == 0) {
        double K = 0, C = 0;
        for (int w = 0; w < 8; w++) { K += (double)s_rk[w]; C += (double)s_rc[w]; }
        g_pair_kl[blockIdx.x]  = K;
        g_pair_cnt[blockIdx.x] = C;
        __threadfence();
        unsigned old = atomicAdd(&g_ticket, 1u);
        s_last = ((old % GRID_PAIR) == GRID_PAIR - 1) ? 1 : 0;
    }
    __syncthreads();
    if (!s_last) return;
    __threadfence();

    // ---- last CTA: reduce all partials, compute final loss ----
    double K = 0, C = 0, Tk = 0, Ef = 0, Ent = 0;
    for (int i = tid; i < GRID_PAIR; i += 256) { K += g_pair_kl[i]; C += g_pair_cnt[i]; }
    for (int i = tid; i < PREP_BLKS; i += 256) {
        Tk += g_pp_task[i]; Ef += g_pp_eff[i]; Ent += g_pp_ent[i];
    }
    double Us = 0;                     // warp w reduces expert w
    for (int i = lane; i < PREP_BLKS; i += 32) Us += (double)g_pp_us[i * EN + wid];

    K = wredd(K); C = wredd(C); Tk = wredd(Tk); Ef = wredd(Ef); Ent = wredd(Ent);
    Us = wredd(Us);
    if (lane == 0) {
        s_fin[0][wid] = K;  s_fin[1][wid] = C;  s_fin[2][wid] = Tk;
        s_fin[3][wid] = Ef; s_fin[4][wid] = Ent; s_fin[5][wid] = Us;
    }
    __syncthreads();
    if (tid == 0) {
        double k = 0, c = 0, tk = 0, ef = 0, en = 0;
        for (int w = 0; w < 8; w++) {
            k += s_fin[0][w]; c += s_fin[1][w]; tk += s_fin[2][w];
            ef += s_fin[3][w]; en += s_fin[4][w];
        }
        double u[EN], mu = 0.0;
        for (int e = 0; e < EN; e++) { u[e] = s_fin[5][e] / (double)BN; mu += u[e]; }
        mu /= (double)EN;
        double var = 0.0;
        for (int e = 0; e < EN; e++) var += (u[e] - mu) * (u[e] - mu);
        var /= (double)(EN - 1);
        double cons = (c > 0.0) ? 0.1 * (k / c) : 0.0;
        double tt = (double)temperature[0] - 1.0;
        double loss = tk / (double)BN
                    + 0.1 * var * (double)(EN * EN)
                    + 0.05 * ef / (double)BN
                    + cons
                    + 0.01 * en / (double)BN
                    + 0.01 * tt * tt;
        out[0] = (float)loss;
    }
}

// ---------------- launch -----------------------------------------------------
extern "C" void kernel_launch(void* const* d_in, const int* in_sizes, int n_in,
                              void* d_out, int out_size) {
    const float* logits  = (const float*)d_in[0];
    const int*   targets = (const int*)d_in[1];
    const float* rp      = (const float*)d_in[2];
    const float* emb     = (const float*)d_in[3];
    const float* temp    = (const float*)d_in[4];
    float* out = (float*)d_out;

    static int s_attr_done = 0;
    if (!s_attr_done) {
        cudaFuncSetAttribute(pair_kernel,
                             cudaFuncAttributeMaxDynamicSharedMemorySize, SM_TOTAL);
        s_attr_done = 1;
    }

    prep_kernel<<<PREP_BLKS, 256>>>(logits, targets, rp, emb);
    pair_kernel<<<GRID_PAIR, 256, SM_TOTAL>>>(temp, out);
}

// round 12
// speedup vs baseline: 1.1154x; 1.1154x over previous
#include <cuda_runtime.h>
#include <cuda_bf16.h>

#define BN 8192
#define EN 8
#define HN 128
#define TS 128
#define NT (BN / TS)                 // 64 tiles per dim
#define NPAIR (NT * (NT + 1) / 2)    // 2080 upper-triangular tile pairs
#define GRID_PAIR 296                // 2 CTAs/SM, one wave
#define PREP_BLKS (BN / 8)           // 1024

// ---------------- device scratch -------------------------------------------
// Fragment-linear bf16 tile images. One "block" = 512 B = one warp fragment
// group: lane l holds 16 B at offset l*16.
//  A image (i-side, m16n8k16 A-frag): block (tile, mt 0..7, s16 0..7)
//    lane l, reg r (4B each): element(row = mt*16 + (r&1)*8 + (l>>2),
//                                      col = s16*16 + (r>>1)*8 + (l&3)*2 (+1))
//  B image (j-side, B-frag, 2 n8-tiles per block): block (tile, pnt 0..7, s16)
//    lane l bytes: [b0 ntl0, b1 ntl0, b0 ntl1, b1 ntl1];
//    b0 = (n = pnt*16 + ntl*8 + (l>>2), k = s16*16 + (l&3)*2), b1 = k+8
__device__ __align__(1024) unsigned char g_A[NT * 64 * 512];   // 2 MB
__device__ __align__(1024) unsigned char g_B[NT * 64 * 512];   // 2 MB
// KL operand images, same fragment layouts, single s16 (16 cols):
//   X_i = [logp_i - a_i (8), p_i (8)] (A-frag), Y_j = [p_j (8), logp_j - a_j (8)] (B-frag)
//   X_i . Y_j = -(kl(i,j) + kl(j,i))   (uses sum_e p = 1)
__device__ __align__(1024) unsigned char g_Xf[NT * 8 * 512];   // 256 KB
__device__ __align__(1024) unsigned char g_Yf[NT * 8 * 512];   // 256 KB
// prep per-block partials (written unconditionally -> no zeroing kernel)
__device__ double g_pp_task[PREP_BLKS], g_pp_eff[PREP_BLKS], g_pp_ent[PREP_BLKS];
__device__ float  g_pp_us[PREP_BLKS * EN];
// pair per-CTA partials + never-reset ticket (modular check is replay-safe)
__device__ double g_pair_kl[GRID_PAIR];
__device__ double g_pair_cnt[GRID_PAIR];
__device__ unsigned g_ticket;

// ---------------- PTX helpers ----------------------------------------------
__device__ __forceinline__ void mma16816(float* d, const unsigned* a, const unsigned* b) {
    asm volatile(
        "mma.sync.aligned.m16n8k16.row.col.f32.bf16.bf16.f32 "
        "{%0,%1,%2,%3}, {%4,%5,%6,%7}, {%8,%9}, {%0,%1,%2,%3};"
        : "+f"(d[0]), "+f"(d[1]), "+f"(d[2]), "+f"(d[3])
        : "r"(a[0]), "r"(a[1]), "r"(a[2]), "r"(a[3]), "r"(b[0]), "r"(b[1]));
}
__device__ __forceinline__ unsigned pkbf(float a, float b) {
    return (unsigned)__bfloat16_as_ushort(__float2bfloat16_rn(a)) |
           ((unsigned)__bfloat16_as_ushort(__float2bfloat16_rn(b)) << 16);
}
__device__ __forceinline__ double wredd(double v) {
#pragma unroll
    for (int o = 16; o > 0; o >>= 1) v += __shfl_xor_sync(0xffffffffu, v, o);
    return v;
}

// ---------------- per-row preprocessing + cheap loss partials ---------------
__global__ __launch_bounds__(256) void prep_kernel(
    const float* __restrict__ logits,
    const int* __restrict__ targets,
    const float* __restrict__ rp,
    const float* __restrict__ emb) {
    int warp = threadIdx.x >> 5, lane = threadIdx.x & 31;
    int row = blockIdx.x * 8 + warp;
    __shared__ float  s_us[EN];
    __shared__ double s_task[8], s_eff[8], s_ent[8];
    if (threadIdx.x < EN) s_us[threadIdx.x] = 0.f;
    __syncthreads();

    // normalize embedding row (float4 per lane = 4 consecutive k-cols)
    float4 v = *(const float4*)(emb + (size_t)row * HN + lane * 4);
    float ss = v.x * v.x + v.y * v.y + v.z * v.z + v.w * v.w;
#pragma unroll
    for (int o = 16; o > 0; o >>= 1) ss += __shfl_xor_sync(0xffffffffu, ss, o);
    float inv = rsqrtf(ss);
    float4 w = make_float4(v.x * inv, v.y * inv, v.z * inv, v.w * inv);

    // write bf16 fragment-linear sim images (A-frag + B-frag)
    {
        int lr   = row & (TS - 1);
        int tile = row >> 7;
        int c0   = lane * 4;                 // cols c0..c0+3, same s16 & khalf
        int s16  = c0 >> 4;
        int kh   = (c0 >> 3) & 1;
        int l0   = ((lr & 7) << 2) | ((c0 & 7) >> 1);   // lanes l0, l0+1
        unsigned w0 = pkbf(w.x, w.y), w1 = pkbf(w.z, w.w);
        int mt = lr >> 4, r8 = (lr >> 3) & 1;
        unsigned baseA = (unsigned)((tile * 64 + mt * 8 + s16) << 9);
        unsigned regA  = (unsigned)(((kh << 1) | r8) << 2);
        *(unsigned*)(g_A + baseA + l0 * 16 + regA)       = w0;
        *(unsigned*)(g_A + baseA + (l0 + 1) * 16 + regA) = w1;
        unsigned baseB = (unsigned)((tile * 64 + mt * 8 + s16) << 9); // pnt==mt
        unsigned innB  = (unsigned)(r8 * 8 + kh * 4);    // ntl==r8
        *(unsigned*)(g_B + baseB + l0 * 16 + innB)       = w0;
        *(unsigned*)(g_B + baseB + (l0 + 1) * 16 + innB) = w1;
    }

    // routing-prob softmax over E=8
    float r = (lane < EN) ? rp[row * EN + lane] : -3.0e38f;
    float m = r;
#pragma unroll
    for (int o = 4; o > 0; o >>= 1) m = fmaxf(m, __shfl_xor_sync(0xffffffffu, m, o));
    float ex = (lane < EN) ? expf(r - m) : 0.f;
    float es = ex;
#pragma unroll
    for (int o = 4; o > 0; o >>= 1) es += __shfl_xor_sync(0xffffffffu, es, o);
    float lse = m + logf(es);
    float lp = r - lse;
    float p  = expf(lp);

    float av  = (lane < EN) ? p * lp : 0.f;
    float evv = (lane < EN && r < 0.1f) ? r : 0.f;
    float nv  = (lane < EN) ? r * logf(r + 1e-8f) : 0.f;
#pragma unroll
    for (int o = 4; o > 0; o >>= 1) {
        av  += __shfl_xor_sync(0xffffffffu, av, o);
        evv += __shfl_xor_sync(0xffffffffu, evv, o);
        nv  += __shfl_xor_sync(0xffffffffu, nv, o);
    }

    // write fragment-linear X/Y KL images (lane e = col-pair index 0..7)
    {
        float l0v = __shfl_sync(0xffffffffu, lp, (lane & 3) * 2);
        float l1v = __shfl_sync(0xffffffffu, lp, (lane & 3) * 2 + 1);
        float p0v = __shfl_sync(0xffffffffu, p,  (lane & 3) * 2);
        float p1v = __shfl_sync(0xffffffffu, p,  (lane & 3) * 2 + 1);
        if (lane < 8) {
            int e = lane;
            unsigned lw = pkbf(l0v - av, l1v - av);
            unsigned pw = pkbf(p0v, p1v);
            unsigned Xw = (e < 4) ? lw : pw;
            unsigned Yw = (e < 4) ? pw : lw;
            int lr = row & (TS - 1), tile = row >> 7;
            int mt = lr >> 4, r8 = (lr >> 3) & 1, kh = e >> 2;
            int lX = ((lr & 7) << 2) | (e & 3);
            unsigned base = (unsigned)((tile * 8 + mt) << 9);
            *(unsigned*)(g_Xf + base + lX * 16 + (((kh << 1) | r8) << 2)) = Xw;
            *(unsigned*)(g_Yf + base + lX * 16 + r8 * 8 + kh * 4)         = Yw;
        }
    }

    if (lane < EN) atomicAdd(&s_us[lane], r);
    if (lane == 0) {
        float l0 = logits[row * 3 + 0], l1 = logits[row * 3 + 1], l2 = logits[row * 3 + 2];
        float mm = fmaxf(l0, fmaxf(l1, l2));
        float lsm = mm + logf(expf(l0 - mm) + expf(l1 - mm) + expf(l2 - mm));
        int t = targets[row];
        float lt = (t == 0) ? l0 : ((t == 1) ? l1 : l2);
        s_task[warp] = (double)(lsm - lt);
        s_eff[warp]  = (double)evv;
        s_ent[warp]  = (double)nv;
    }
    __syncthreads();
    if (threadIdx.x == 0) {
        double a = 0, b = 0, c = 0;
        for (int i = 0; i < 8; i++) { a += s_task[i]; b += s_eff[i]; c += s_ent[i]; }
        g_pp_task[blockIdx.x] = a;
        g_pp_eff[blockIdx.x]  = b;
        g_pp_ent[blockIdx.x]  = c;
    }
    if (threadIdx.x < EN) g_pp_us[blockIdx.x * EN + threadIdx.x] = s_us[threadIdx.x];
}

// ---------------- pair kernel: direct-LDG fragment GEMM, zero barriers ------
// Fragments loaded straight from L2-resident fragment-linear images with
// LDG.128; no smem staging, no cp.async, no mainloop __syncthreads.
// Epilogue: mask pack + ONE bf16 K=16 GEMM D = X_i x Y_j^T = -(kl+kl'),
// masked fold, 0.5x on diagonal tiles.
__global__ __launch_bounds__(256, 2) void pair_kernel(
    const float* __restrict__ temperature, float* __restrict__ out) {
    __shared__ float s_rk[8];
    __shared__ int   s_rc[8];
    __shared__ double s_fin[6][8];
    __shared__ int s_last;

    int tid  = threadIdx.x;
    int wid  = tid >> 5;
    int lane = tid & 31;

    int mt0 = (wid & 3) * 2;        // warp's first m16-tile (of 8)
    int pn0 = (wid >> 2) * 4;       // warp's first pnt block (of 8)
    int mbase = mt0 * 16;
    int nbase = pn0 * 16;

    float kls = 0.f;
    int   cnt = 0;

    // decode first tile
    int ti = 0, rem = blockIdx.x;
    while (rem >= NT - ti) { rem -= NT - ti; ti++; }
    int tj = ti + rem;

    for (int t = blockIdx.x; t < NPAIR; t += GRID_PAIR) {
        bool diag = (ti == tj);
        int ti2 = ti, tj2 = tj;
        if (t + GRID_PAIR < NPAIR) {
            int a = 0, r2 = t + GRID_PAIR;
            while (r2 >= NT - a) { r2 -= NT - a; a++; }
            ti2 = a; tj2 = a + r2;
        }

        const uint4* Ab = (const uint4*)g_A + ((size_t)ti << 11) + lane; // 64 blk * 32
        const uint4* Bb = (const uint4*)g_B + ((size_t)tj << 11) + lane;

        float acc[2][8][4];
#pragma unroll
        for (int a = 0; a < 2; a++)
#pragma unroll
            for (int b = 0; b < 8; b++)
#pragma unroll
                for (int c = 0; c < 4; c++) acc[a][b][c] = 0.f;

#pragma unroll
        for (int s = 0; s < 8; s++) {
            uint4 a0 = __ldg(Ab + ((mt0 + 0) * 8 + s) * 32);
            uint4 a1 = __ldg(Ab + ((mt0 + 1) * 8 + s) * 32);
            uint4 b0 = __ldg(Bb + ((pn0 + 0) * 8 + s) * 32);
            uint4 b1 = __ldg(Bb + ((pn0 + 1) * 8 + s) * 32);
            uint4 b2 = __ldg(Bb + ((pn0 + 2) * 8 + s) * 32);
            uint4 b3 = __ldg(Bb + ((pn0 + 3) * 8 + s) * 32);
            const unsigned* af0 = (const unsigned*)&a0;
            const unsigned* af1 = (const unsigned*)&a1;
            const unsigned* bp[4] = { (const unsigned*)&b0, (const unsigned*)&b1,
                                      (const unsigned*)&b2, (const unsigned*)&b3 };
#pragma unroll
            for (int pnt = 0; pnt < 4; pnt++) {
                mma16816(acc[0][pnt * 2 + 0], af0, bp[pnt] + 0);
                mma16816(acc[0][pnt * 2 + 1], af0, bp[pnt] + 2);
                mma16816(acc[1][pnt * 2 + 0], af1, bp[pnt] + 0);
                mma16816(acc[1][pnt * 2 + 1], af1, bp[pnt] + 2);
            }
        }

        // ---- pack threshold masks (diag branch hoisted) ----
        unsigned msk[2];
        if (!diag) {
#pragma unroll
            for (int mt = 0; mt < 2; mt++) {
                unsigned mw = 0;
#pragma unroll
                for (int nt = 0; nt < 8; nt++)
#pragma unroll
                    for (int q = 0; q < 4; q++)
                        mw |= (acc[mt][nt][q] > 0.8f ? 1u : 0u) << (nt * 4 + q);
                msk[mt] = mw;
            }
            cnt += 2 * (__popc(msk[0]) + __popc(msk[1]));
        } else {
#pragma unroll
            for (int mt = 0; mt < 2; mt++) {
                unsigned mw = 0;
#pragma unroll
                for (int nt = 0; nt < 8; nt++)
#pragma unroll
                    for (int q = 0; q < 4; q++) {
                        int il = mbase + mt * 16 + (q >> 1) * 8 + (lane >> 2);
                        int jl = nbase + nt * 8 + (lane & 3) * 2 + (q & 1);
                        bool pass = (acc[mt][nt][q] > 0.8f) && (il != jl);
                        mw |= (pass ? 1u : 0u) << (nt * 4 + q);
                    }
                msk[mt] = mw;
            }
            cnt += __popc(msk[0]) + __popc(msk[1]);
        }

        // ---- ONE bf16 K=16 GEMM: D = X_i x Y_j^T = -(kl(i,j)+kl(j,i)) ----
#pragma unroll
        for (int a = 0; a < 2; a++)
#pragma unroll
            for (int b = 0; b < 8; b++)
#pragma unroll
                for (int c = 0; c < 4; c++) acc[a][b][c] = 0.f;
        {
            const uint4* Xb = (const uint4*)g_Xf + ((size_t)ti << 8) + lane; // 8 blk * 32
            const uint4* Yb = (const uint4*)g_Yf + ((size_t)tj << 8) + lane;
            uint4 xa0 = __ldg(Xb + (mt0 + 0) * 32);
            uint4 xa1 = __ldg(Xb + (mt0 + 1) * 32);
            uint4 yb0 = __ldg(Yb + (pn0 + 0) * 32);
            uint4 yb1 = __ldg(Yb + (pn0 + 1) * 32);
            uint4 yb2 = __ldg(Yb + (pn0 + 2) * 32);
            uint4 yb3 = __ldg(Yb + (pn0 + 3) * 32);
            const unsigned* xf0 = (const unsigned*)&xa0;
            const unsigned* xf1 = (const unsigned*)&xa1;
            const unsigned* yp[4] = { (const unsigned*)&yb0, (const unsigned*)&yb1,
                                      (const unsigned*)&yb2, (const unsigned*)&yb3 };
#pragma unroll
            for (int pnt = 0; pnt < 4; pnt++) {
                mma16816(acc[0][pnt * 2 + 0], xf0, yp[pnt] + 0);
                mma16816(acc[0][pnt * 2 + 1], xf0, yp[pnt] + 2);
                mma16816(acc[1][pnt * 2 + 0], xf1, yp[pnt] + 0);
                mma16816(acc[1][pnt * 2 + 1], xf1, yp[pnt] + 2);
            }
        }
        float S = 0.f;
#pragma unroll
        for (int mt = 0; mt < 2; mt++)
#pragma unroll
            for (int nt = 0; nt < 8; nt++)
#pragma unroll
                for (int q = 0; q < 4; q++)
                    S += ((msk[mt] >> (nt * 4 + q)) & 1u) ? acc[mt][nt][q] : 0.f;
        kls -= diag ? 0.5f * S : S;    // D = -(kl sum); diag double-counts pairs

        ti = ti2; tj = tj2;
    }

    // ---- flush per-CTA partial ----
#pragma unroll
    for (int o = 16; o > 0; o >>= 1) {
        kls += __shfl_xor_sync(0xffffffffu, kls, o);
        cnt += __shfl_xor_sync(0xffffffffu, cnt, o);
    }
    if (lane == 0) { s_rk[wid] = kls; s_rc[wid] = cnt; }
    __syncthreads();
    if (tid == 0) {
        double K = 0, C = 0;
        for (int w = 0; w < 8; w++) { K += (double)s_rk[w]; C += (double)s_rc[w]; }
        g_pair_kl[blockIdx.x]  = K;
        g_pair_cnt[blockIdx.x] = C;
        __threadfence();
        unsigned old = atomicAdd(&g_ticket, 1u);
        s_last = ((old % GRID_PAIR) == GRID_PAIR - 1) ? 1 : 0;
    }
    __syncthreads();
    if (!s_last) return;
    __threadfence();

    // ---- last CTA: reduce all partials, compute final loss ----
    double K = 0, C = 0, Tk = 0, Ef = 0, Ent = 0;
    for (int i = tid; i < GRID_PAIR; i += 256) { K += g_pair_kl[i]; C += g_pair_cnt[i]; }
    for (int i = tid; i < PREP_BLKS; i += 256) {
        Tk += g_pp_task[i]; Ef += g_pp_eff[i]; Ent += g_pp_ent[i];
    }
    double Us = 0;                     // warp w reduces expert w
    for (int i = lane; i < PREP_BLKS; i += 32) Us += (double)g_pp_us[i * EN + wid];

    K = wredd(K); C = wredd(C); Tk = wredd(Tk); Ef = wredd(Ef); Ent = wredd(Ent);
    Us = wredd(Us);
    if (lane == 0) {
        s_fin[0][wid] = K;  s_fin[1][wid] = C;  s_fin[2][wid] = Tk;
        s_fin[3][wid] = Ef; s_fin[4][wid] = Ent; s_fin[5][wid] = Us;
    }
    __syncthreads();
    if (tid == 0) {
        double k = 0, c = 0, tk = 0, ef = 0, en = 0;
        for (int w = 0; w < 8; w++) {
            k += s_fin[0][w]; c += s_fin[1][w]; tk += s_fin[2][w];
            ef += s_fin[3][w]; en += s_fin[4][w];
        }
        double u[EN], mu = 0.0;
        for (int e = 0; e < EN; e++) { u[e] = s_fin[5][e] / (double)BN; mu += u[e]; }
        mu /= (double)EN;
        double var = 0.0;
        for (int e = 0; e < EN; e++) var += (u[e] - mu) * (u[e] - mu);
        var /= (double)(EN - 1);
        double cons = (c > 0.0) ? 0.1 * (k / c) : 0.0;
        double tt = (double)temperature[0] - 1.0;
        double loss = tk / (double)BN
                    + 0.1 * var * (double)(EN * EN)
                    + 0.05 * ef / (double)BN
                    + cons
                    + 0.01 * en / (double)BN
                    + 0.01 * tt * tt;
        out[0] = (float)loss;
    }
}

// ---------------- launch -----------------------------------------------------
extern "C" void kernel_launch(void* const* d_in, const int* in_sizes, int n_in,
                              void* d_out, int out_size) {
    const float* logits  = (const float*)d_in[0];
    const int*   targets = (const int*)d_in[1];
    const float* rp      = (const float*)d_in[2];
    const float* emb     = (const float*)d_in[3];
    const float* temp    = (const float*)d_in[4];
    float* out = (float*)d_out;

    prep_kernel<<<PREP_BLKS, 256>>>(logits, targets, rp, emb);
    pair_kernel<<<GRID_PAIR, 256>>>(temp, out);
}